// round 14
// baseline (speedup 1.0000x reference)
#include <cuda_runtime.h>
#include <cuda_bf16.h>
#include <cstdint>

#define Bsz 8
#define CI  512
#define CO  256
#define NN  2048

// ---------------- scratch (device globals, bf16) ----------------
__device__ unsigned short g_Xt[(size_t)Bsz * NN * CI];  // [b][n][ci]
__device__ unsigned short g_Qx[(size_t)Bsz * NN * CI];  // [b][n][ci] (query input)
__device__ unsigned short g_Wk[CO * CI];
__device__ unsigned short g_Wq[CO * CI];
__device__ unsigned short g_Wv[CO * CI];
__device__ unsigned short g_Wu[CI * CO];
__device__ unsigned short g_Kt[(size_t)Bsz * NN * CO];  // [b][n][co], pre-scaled 1/16
__device__ unsigned short g_Qt[(size_t)Bsz * NN * CO];  // [b][n][co]
__device__ unsigned short g_V [(size_t)Bsz * CO * NN];  // [b][co][n]
__device__ unsigned short g_S [(size_t)Bsz * NN * NN];  // [b][n][m] exp(logits)
__device__ unsigned short g_Ot[(size_t)Bsz * NN * CO];  // [b][n2][co2] (written by av directly)
__device__ float          g_rowsum[(size_t)Bsz * NN];

// ---------------- helpers ----------------
__device__ __forceinline__ uint32_t smem_u32(const void* p) {
    uint32_t a;
    asm("{ .reg .u64 t; cvta.to.shared.u64 t, %1; cvt.u32.u64 %0, t; }" : "=r"(a) : "l"(p));
    return a;
}
__device__ __forceinline__ void ldmatrix_x4(uint32_t* r, uint32_t addr) {
    asm volatile("ldmatrix.sync.aligned.m8n8.x4.shared.b16 {%0,%1,%2,%3}, [%4];"
                 : "=r"(r[0]), "=r"(r[1]), "=r"(r[2]), "=r"(r[3]) : "r"(addr));
}
__device__ __forceinline__ void mma16816(float* d, const uint32_t* a, const uint32_t* b) {
    asm volatile(
        "mma.sync.aligned.m16n8k16.row.col.f32.bf16.bf16.f32 "
        "{%0,%1,%2,%3}, {%4,%5,%6,%7}, {%8,%9}, {%0,%1,%2,%3};"
        : "+f"(d[0]), "+f"(d[1]), "+f"(d[2]), "+f"(d[3])
        : "r"(a[0]), "r"(a[1]), "r"(a[2]), "r"(a[3]), "r"(b[0]), "r"(b[1]));
}
__device__ __forceinline__ void st_bf16x2(unsigned short* dst, float v0, float v1) {
    __nv_bfloat162 h = __floats2bfloat162_rn(v0, v1);
    *reinterpret_cast<uint32_t*>(dst) = *reinterpret_cast<uint32_t*>(&h);
}
__device__ __forceinline__ unsigned short f2bf(float v) {
    __nv_bfloat16 h = __float2bfloat16(v);
    return *reinterpret_cast<unsigned short*>(&h);
}

// smem tile: 128 rows x 64 halves (BK), padded to 72 halves = 144 B/row (9x16B)
#define BK      64
#define ROWB    144
#define TILE_H  (128 * 72)
#define STAGE_H (2 * TILE_H)
#define NSTAGE  3
#define SMEM_BYTES (NSTAGE * STAGE_H * 2)   // 110592

// 128x64 bf16 tile via cp.async: 1024 16-byte chunks, 4 per thread
__device__ __forceinline__ void cp_tile(uint32_t sb, const unsigned short* __restrict__ src,
                                        int ld, int tid) {
#pragma unroll
    for (int i = 0; i < 4; i++) {
        int ch = tid + i * 256;
        int row = ch >> 3, c = ch & 7;
        uint32_t sa = sb + row * ROWB + c * 16;
        const void* ga = src + (size_t)row * ld + c * 8;
        asm volatile("cp.async.cg.shared.global [%0], [%1], 16;" :: "r"(sa), "l"(ga));
    }
}

// ---------------- 3-stage pipelined 128x128 HMMA GEMM, BK=64 (R8/R12 engine) ----------------
// NOTE: syncs all threads before the epilogue so fe may safely reuse the pipeline smem.
template <class FE>
__device__ __forceinline__ void gemm_body(int ktiles,
        const unsigned short* __restrict__ Ag, int lda,
        const unsigned short* __restrict__ Bg, int ldb, FE fe) {
    extern __shared__ __align__(16) unsigned short sm[];
    const int tid = threadIdx.x, wid = tid >> 5, lane = tid & 31;
    const int wm = (wid & 3) * 32, wn = (wid >> 2) * 64;

    float acc[2][8][4];
#pragma unroll
    for (int mt = 0; mt < 2; mt++)
#pragma unroll
        for (int nt = 0; nt < 8; nt++)
#pragma unroll
            for (int j = 0; j < 4; j++) acc[mt][nt][j] = 0.f;

#pragma unroll
    for (int s = 0; s < 2; s++) {
        uint32_t sb = smem_u32(sm + s * STAGE_H);
        cp_tile(sb, Ag + (size_t)s * BK, lda, tid);
        cp_tile(sb + TILE_H * 2, Bg + (size_t)s * BK, ldb, tid);
        asm volatile("cp.async.commit_group;" ::: "memory");
    }

    int stage = 0;
    for (int kt = 0; kt < ktiles; kt++) {
        if (kt == ktiles - 1) asm volatile("cp.async.wait_group 0;" ::: "memory");
        else                  asm volatile("cp.async.wait_group 1;" ::: "memory");
        __syncthreads();

        if (kt + 2 < ktiles) {
            int ps = stage + 2; if (ps >= NSTAGE) ps -= NSTAGE;
            uint32_t sb = smem_u32(sm + ps * STAGE_H);
            cp_tile(sb, Ag + (size_t)(kt + 2) * BK, lda, tid);
            cp_tile(sb + TILE_H * 2, Bg + (size_t)(kt + 2) * BK, ldb, tid);
            asm volatile("cp.async.commit_group;" ::: "memory");
        }

        const uint32_t aB = smem_u32(sm + stage * STAGE_H);
        const uint32_t bB = aB + TILE_H * 2;
#pragma unroll
        for (int ks = 0; ks < 4; ks++) {
            uint32_t a[2][4];
#pragma unroll
            for (int mt = 0; mt < 2; mt++) {
                uint32_t addr = aB + (wm + mt * 16 + (lane & 15)) * ROWB
                              + (ks * 16 + ((lane >> 4) << 3)) * 2;
                ldmatrix_x4(a[mt], addr);
            }
            uint32_t b[8][2];
#pragma unroll
            for (int np = 0; np < 4; np++) {
                uint32_t r[4];
                int row = wn + np * 16 + ((lane >> 4) << 3) + (lane & 7);
                int koff = ks * 16 + (((lane >> 3) & 1) << 3);
                ldmatrix_x4(r, bB + row * ROWB + koff * 2);
                b[2 * np][0] = r[0]; b[2 * np][1] = r[1];
                b[2 * np + 1][0] = r[2]; b[2 * np + 1][1] = r[3];
            }
#pragma unroll
            for (int mt = 0; mt < 2; mt++)
#pragma unroll
                for (int nt = 0; nt < 8; nt++)
                    mma16816(acc[mt][nt], a[mt], b[nt]);
        }
        if (++stage == NSTAGE) stage = 0;
    }

    __syncthreads();   // pipeline smem free for epilogue reuse
#pragma unroll
    for (int mt = 0; mt < 2; mt++) {
        int r0 = wm + mt * 16 + (lane >> 2);
#pragma unroll
        for (int nt = 0; nt < 8; nt++)
            fe(r0, wn + nt * 8 + ((lane & 3) << 1), acc[mt][nt]);
    }
}

// ---------------- merged prep: input transpose + weight cvt + rowsum zero ----------------
// grid (64, 16, 17): z<16 -> transpose slice (b = z>>1, which = z&1); z==16 -> weights+rowsum
__global__ __launch_bounds__(256)
void prep_kernel(const float* __restrict__ x, const float* __restrict__ query,
                 const float* __restrict__ kw, const float* __restrict__ qw,
                 const float* __restrict__ vw, const float* __restrict__ uw) {
    int z = blockIdx.z;
    if (z == 16) {
        int idx = (blockIdx.y * 64 + blockIdx.x) * 256 + threadIdx.x;  // [0, 262144)
#pragma unroll
        for (int h = 0; h < 2; h++) {
            int i = idx + h * 262144;
            int seg = i >> 17, off = i & 131071;
            const float* src = seg == 0 ? kw : seg == 1 ? qw : seg == 2 ? vw : uw;
            unsigned short* dst = seg == 0 ? g_Wk : seg == 1 ? g_Wq : seg == 2 ? g_Wv : g_Wu;
            dst[off] = f2bf(src[off]);
        }
        if (idx < Bsz * NN) g_rowsum[idx] = 0.f;
        return;
    }
    int b = z >> 1, which = z & 1;
    const float* src = (which ? query : x) + (size_t)b * CI * NN;
    unsigned short* dst = (which ? g_Qx : g_Xt) + (size_t)b * NN * CI;
    __shared__ unsigned short t[32][33];
    int n0 = blockIdx.x * 32, c0 = blockIdx.y * 32;
    int tx = threadIdx.x & 31, ty = threadIdx.x >> 5;
#pragma unroll
    for (int j = 0; j < 4; j++) {
        int ci = c0 + ty + j * 8;
        t[ty + j * 8][tx] = f2bf(src[(size_t)ci * NN + n0 + tx]);
    }
    __syncthreads();
#pragma unroll
    for (int j = 0; j < 4; j++)
        dst[(size_t)(n0 + ty + j * 8) * CI + c0 + tx] = t[tx][ty + j * 8];
}

// ---------------- Stage 1: ALL projections in one launch ----------------
// z = b*3 + which; which: 0=K -> [n][co]*1/16, 1=Q -> [n][co], 2=V -> [co][n]
__global__ __launch_bounds__(256, 2)
void proj_kernel(const float* __restrict__ kb, const float* __restrict__ qb,
                 const float* __restrict__ vb) {
    int z = blockIdx.z, b = z / 3, which = z - b * 3;
    int co0 = blockIdx.x * 128, n0 = blockIdx.y * 128;

    if (which == 2) {
        const unsigned short* X = g_Xt + (size_t)b * NN * CI;
        unsigned short* out = g_V + (size_t)b * CO * NN;
        gemm_body(CI / BK, g_Wv + (size_t)co0 * CI, CI, X + (size_t)n0 * CI, CI,
            [&](int row, int col, const float* v) {
                float bv0 = vb[co0 + row], bv1 = vb[co0 + row + 8];
                st_bf16x2(out + (size_t)(co0 + row) * NN + n0 + col, v[0] + bv0, v[1] + bv0);
                st_bf16x2(out + (size_t)(co0 + row + 8) * NN + n0 + col, v[2] + bv1, v[3] + bv1);
            });
    } else {
        const unsigned short* X = (which ? g_Qx : g_Xt) + (size_t)b * NN * CI;
        const unsigned short* W = which ? g_Wq : g_Wk;
        const float* bias = which ? qb : kb;
        unsigned short* out = (which ? g_Qt : g_Kt) + (size_t)b * NN * CO;
        float scale = which ? 1.0f : 0.0625f;
        gemm_body(CI / BK, X + (size_t)n0 * CI, CI, W + (size_t)co0 * CI, CI,
            [&](int row, int col, const float* v) {
                float b0 = bias[co0 + col], b1 = bias[co0 + col + 1];
                st_bf16x2(out + (size_t)(n0 + row) * CO + co0 + col,
                          (v[0] + b0) * scale, (v[1] + b1) * scale);
                st_bf16x2(out + (size_t)(n0 + row + 8) * CO + co0 + col,
                          (v[2] + b0) * scale, (v[3] + b1) * scale);
            });
    }
}

// ---------------- Stage 2: S = exp(K.Q/16), rowsum via atomics ----------------
__global__ __launch_bounds__(256, 2)
void qk_kernel() {
    int b = blockIdx.z;
    const unsigned short* Kt = g_Kt + (size_t)b * NN * CO;
    const unsigned short* Qt = g_Qt + (size_t)b * NN * CO;
    unsigned short* S = g_S + (size_t)b * NN * NN;
    int m0 = blockIdx.x * 128, n0 = blockIdx.y * 128;

    float rs[4] = {0.f, 0.f, 0.f, 0.f};
    gemm_body(CO / BK, Kt + (size_t)n0 * CO, CO, Qt + (size_t)m0 * CO, CO,
        [&](int row, int col, const float* v) {
            float e0 = __expf(v[0]), e1 = __expf(v[1]);
            float e2 = __expf(v[2]), e3 = __expf(v[3]);
            st_bf16x2(S + (size_t)(n0 + row) * NN + m0 + col, e0, e1);
            st_bf16x2(S + (size_t)(n0 + row + 8) * NN + m0 + col, e2, e3);
            rs[(row >> 3) & 3] += e0 + e1;
            rs[((row >> 3) & 3) | 1] += e2 + e3;
        });

    int lane = threadIdx.x & 31, wid = threadIdx.x >> 5;
    int wm = (wid & 3) * 32, q = lane >> 2;
#pragma unroll
    for (int i = 0; i < 4; i++) {
        float s = rs[i];
        s += __shfl_xor_sync(0xffffffffu, s, 1);
        s += __shfl_xor_sync(0xffffffffu, s, 2);
        if ((lane & 3) == 0) {
            int row = wm + (i >> 1) * 16 + (i & 1) * 8 + q;
            atomicAdd(&g_rowsum[(size_t)b * NN + n0 + row], s);
        }
    }
}

// ---------------- Stage 3: O/rowsum, written DIRECTLY transposed into Ot ----------------
// Tile O[n0+128)[c0+128) maps to Ot[(n&7)*256 + co][n>>3]: stage in smem sT[col][row]
// (row length 130 halves -> stride 65 words, conflict-free), then write 32B segments.
#define SROW 130
__global__ __launch_bounds__(256, 2)
void av_kernel() {
    int b = blockIdx.z;
    const unsigned short* P = g_S + (size_t)b * NN * NN;
    const unsigned short* V = g_V + (size_t)b * CO * NN;
    const float* rsum = g_rowsum + (size_t)b * NN;
    unsigned short* Ot = g_Ot + (size_t)b * NN * CO;
    int c0 = blockIdx.x * 128, n0 = blockIdx.y * 128;
    extern __shared__ __align__(16) unsigned short sm[];
    unsigned short* sT = sm;   // [128 cols][SROW] halves (33280 B, inside pipeline smem)

    gemm_body(NN / BK, P + (size_t)n0 * NN, NN, V + (size_t)c0 * NN, NN,
        [&](int row, int col, const float* v) {
            float i0 = 1.0f / rsum[n0 + row];
            float i1 = 1.0f / rsum[n0 + row + 8];
            sT[col * SROW + row]           = f2bf(v[0] * i0);
            sT[(col + 1) * SROW + row]     = f2bf(v[1] * i0);
            sT[col * SROW + row + 8]       = f2bf(v[2] * i1);
            sT[(col + 1) * SROW + row + 8] = f2bf(v[3] * i1);
        });
    __syncthreads();

    int tid = threadIdx.x;
    int co2base = n0 >> 3;
#pragma unroll
    for (int i = 0; i < 4; i++) {
        int seg = tid + i * 256;           // [0,1024): q = n&7, c = co offset
        int q = seg >> 7, c = seg & 127;
        unsigned short vals[16];
#pragma unroll
        for (int s = 0; s < 16; s++)
            vals[s] = sT[c * SROW + q + 8 * s];   // row n = q + 8s -> co2 = co2base + s
        unsigned short* dst = Ot + (size_t)(q * 256 + c0 + c) * CO + co2base;
        uint4* d4 = reinterpret_cast<uint4*>(dst);
        d4[0] = *reinterpret_cast<uint4*>(vals);
        d4[1] = *reinterpret_cast<uint4*>(vals + 8);
    }
}

// ---------------- Stage 4: up-proj + residual ----------------
__global__ __launch_bounds__(256, 2)
void up_kernel(const float* __restrict__ x, const float* __restrict__ up_b,
               const float* __restrict__ scaling, float* __restrict__ outp) {
    int b = blockIdx.z;
    const unsigned short* Ot = g_Ot + (size_t)b * NN * CO;
    const float* X = x + (size_t)b * CI * NN;
    float* R = outp + (size_t)b * CI * NN;
    int n0 = blockIdx.x * 128, ci0 = blockIdx.y * 128;
    float s = *scaling;

    gemm_body(CO / BK, g_Wu + (size_t)ci0 * CO, CO, Ot + (size_t)n0 * CO, CO,
        [&](int row, int col, const float* v) {
#pragma unroll
            for (int h = 0; h < 2; h++) {
                int ci = ci0 + row + h * 8;
                float bb = up_b[ci];
                const float2 xv = *reinterpret_cast<const float2*>(X + (size_t)ci * NN + n0 + col);
                float2 o;
                o.x = xv.x + s * (v[2 * h] + bb);
                o.y = xv.y + s * (v[2 * h + 1] + bb);
                *reinterpret_cast<float2*>(R + (size_t)ci * NN + n0 + col) = o;
            }
        });
}

// ---------------- launch ----------------
extern "C" void kernel_launch(void* const* d_in, const int* in_sizes, int n_in,
                              void* d_out, int out_size) {
    const float* x       = (const float*)d_in[0];
    const float* query   = (const float*)d_in[1];
    const float* key_w   = (const float*)d_in[2];
    const float* key_b   = (const float*)d_in[3];
    const float* val_w   = (const float*)d_in[4];
    const float* val_b   = (const float*)d_in[5];
    const float* query_w = (const float*)d_in[6];
    const float* query_b = (const float*)d_in[7];
    const float* up_w    = (const float*)d_in[8];
    const float* up_b    = (const float*)d_in[9];
    const float* scaling = (const float*)d_in[10];
    float* out = (float*)d_out;

    cudaFuncSetAttribute(proj_kernel, cudaFuncAttributeMaxDynamicSharedMemorySize, SMEM_BYTES);
    cudaFuncSetAttribute(qk_kernel,   cudaFuncAttributeMaxDynamicSharedMemorySize, SMEM_BYTES);
    cudaFuncSetAttribute(av_kernel,   cudaFuncAttributeMaxDynamicSharedMemorySize, SMEM_BYTES);
    cudaFuncSetAttribute(up_kernel,   cudaFuncAttributeMaxDynamicSharedMemorySize, SMEM_BYTES);

    prep_kernel<<<dim3(NN / 32, CI / 32, Bsz * 2 + 1), 256>>>(x, query, key_w, query_w,
                                                              val_w, up_w);
    proj_kernel<<<dim3(CO / 128, NN / 128, Bsz * 3), 256, SMEM_BYTES>>>(key_b, query_b, val_b);
    qk_kernel<<<dim3(NN / 128, NN / 128, Bsz), 256, SMEM_BYTES>>>();
    av_kernel<<<dim3(CO / 128, NN / 128, Bsz), 256, SMEM_BYTES>>>();
    up_kernel<<<dim3(NN / 128, CI / 128, Bsz), 256, SMEM_BYTES>>>(x, up_b, scaling, out);
}

// round 16
// speedup vs baseline: 1.0199x; 1.0199x over previous
#include <cuda_runtime.h>
#include <cuda_bf16.h>
#include <cstdint>

#define Bsz 8
#define CI  512
#define CO  256
#define NN  2048

// ---------------- scratch (device globals, bf16) ----------------
__device__ unsigned short g_Xt[(size_t)Bsz * NN * CI];  // [b][n][ci]
__device__ unsigned short g_Qx[(size_t)Bsz * NN * CI];  // [b][n][ci] (query input)
__device__ unsigned short g_Wk[CO * CI];
__device__ unsigned short g_Wq[CO * CI];
__device__ unsigned short g_Wv[CO * CI];
__device__ unsigned short g_Wu[CI * CO];
__device__ unsigned short g_Kt[(size_t)Bsz * NN * CO];  // [b][n][co], pre-scaled 1/16
__device__ unsigned short g_Qt[(size_t)Bsz * NN * CO];  // [b][n][co]
__device__ unsigned short g_V [(size_t)Bsz * CO * NN];  // [b][co][n]
__device__ unsigned short g_S [(size_t)Bsz * NN * NN];  // [b][n][m] exp(logits)
__device__ unsigned short g_Ot[(size_t)Bsz * NN * CO];  // [b][n2][co2] (written by av directly)
__device__ float          g_rowsum[(size_t)Bsz * NN];

// ---------------- helpers ----------------
__device__ __forceinline__ uint32_t smem_u32(const void* p) {
    uint32_t a;
    asm("{ .reg .u64 t; cvta.to.shared.u64 t, %1; cvt.u32.u64 %0, t; }" : "=r"(a) : "l"(p));
    return a;
}
__device__ __forceinline__ void ldmatrix_x4(uint32_t* r, uint32_t addr) {
    asm volatile("ldmatrix.sync.aligned.m8n8.x4.shared.b16 {%0,%1,%2,%3}, [%4];"
                 : "=r"(r[0]), "=r"(r[1]), "=r"(r[2]), "=r"(r[3]) : "r"(addr));
}
__device__ __forceinline__ void mma16816(float* d, const uint32_t* a, const uint32_t* b) {
    asm volatile(
        "mma.sync.aligned.m16n8k16.row.col.f32.bf16.bf16.f32 "
        "{%0,%1,%2,%3}, {%4,%5,%6,%7}, {%8,%9}, {%0,%1,%2,%3};"
        : "+f"(d[0]), "+f"(d[1]), "+f"(d[2]), "+f"(d[3])
        : "r"(a[0]), "r"(a[1]), "r"(a[2]), "r"(a[3]), "r"(b[0]), "r"(b[1]));
}
__device__ __forceinline__ void st_bf16x2(unsigned short* dst, float v0, float v1) {
    __nv_bfloat162 h = __floats2bfloat162_rn(v0, v1);
    *reinterpret_cast<uint32_t*>(dst) = *reinterpret_cast<uint32_t*>(&h);
}
__device__ __forceinline__ unsigned short f2bf(float v) {
    __nv_bfloat16 h = __float2bfloat16(v);
    return *reinterpret_cast<unsigned short*>(&h);
}

// smem tile: 128 rows x 64 halves (BK), padded to 72 halves = 144 B/row (9x16B)
#define BK      64
#define ROWB    144
#define TILE_H  (128 * 72)
#define STAGE_H (2 * TILE_H)
#define NSTAGE  3
#define SMEM_BYTES (NSTAGE * STAGE_H * 2)   // 110592

// 128x64 bf16 tile via cp.async: 1024 16-byte chunks, 4 per thread
__device__ __forceinline__ void cp_tile(uint32_t sb, const unsigned short* __restrict__ src,
                                        int ld, int tid) {
#pragma unroll
    for (int i = 0; i < 4; i++) {
        int ch = tid + i * 256;
        int row = ch >> 3, c = ch & 7;
        uint32_t sa = sb + row * ROWB + c * 16;
        const void* ga = src + (size_t)row * ld + c * 8;
        asm volatile("cp.async.cg.shared.global [%0], [%1], 16;" :: "r"(sa), "l"(ga));
    }
}

// ---------------- 3-stage pipelined 128x128 HMMA GEMM, BK=64 (R8/R12 engine) ----------------
// NOTE: syncs all threads before the epilogue so fe may safely reuse the pipeline smem.
template <class FE>
__device__ __forceinline__ void gemm_body(int ktiles,
        const unsigned short* __restrict__ Ag, int lda,
        const unsigned short* __restrict__ Bg, int ldb, FE fe) {
    extern __shared__ __align__(16) unsigned short sm[];
    const int tid = threadIdx.x, wid = tid >> 5, lane = tid & 31;
    const int wm = (wid & 3) * 32, wn = (wid >> 2) * 64;

    float acc[2][8][4];
#pragma unroll
    for (int mt = 0; mt < 2; mt++)
#pragma unroll
        for (int nt = 0; nt < 8; nt++)
#pragma unroll
            for (int j = 0; j < 4; j++) acc[mt][nt][j] = 0.f;

#pragma unroll
    for (int s = 0; s < 2; s++) {
        uint32_t sb = smem_u32(sm + s * STAGE_H);
        cp_tile(sb, Ag + (size_t)s * BK, lda, tid);
        cp_tile(sb + TILE_H * 2, Bg + (size_t)s * BK, ldb, tid);
        asm volatile("cp.async.commit_group;" ::: "memory");
    }

    int stage = 0;
    for (int kt = 0; kt < ktiles; kt++) {
        if (kt == ktiles - 1) asm volatile("cp.async.wait_group 0;" ::: "memory");
        else                  asm volatile("cp.async.wait_group 1;" ::: "memory");
        __syncthreads();

        if (kt + 2 < ktiles) {
            int ps = stage + 2; if (ps >= NSTAGE) ps -= NSTAGE;
            uint32_t sb = smem_u32(sm + ps * STAGE_H);
            cp_tile(sb, Ag + (size_t)(kt + 2) * BK, lda, tid);
            cp_tile(sb + TILE_H * 2, Bg + (size_t)(kt + 2) * BK, ldb, tid);
            asm volatile("cp.async.commit_group;" ::: "memory");
        }

        const uint32_t aB = smem_u32(sm + stage * STAGE_H);
        const uint32_t bB = aB + TILE_H * 2;
#pragma unroll
        for (int ks = 0; ks < 4; ks++) {
            uint32_t a[2][4];
#pragma unroll
            for (int mt = 0; mt < 2; mt++) {
                uint32_t addr = aB + (wm + mt * 16 + (lane & 15)) * ROWB
                              + (ks * 16 + ((lane >> 4) << 3)) * 2;
                ldmatrix_x4(a[mt], addr);
            }
            uint32_t b[8][2];
#pragma unroll
            for (int np = 0; np < 4; np++) {
                uint32_t r[4];
                int row = wn + np * 16 + ((lane >> 4) << 3) + (lane & 7);
                int koff = ks * 16 + (((lane >> 3) & 1) << 3);
                ldmatrix_x4(r, bB + row * ROWB + koff * 2);
                b[2 * np][0] = r[0]; b[2 * np][1] = r[1];
                b[2 * np + 1][0] = r[2]; b[2 * np + 1][1] = r[3];
            }
#pragma unroll
            for (int mt = 0; mt < 2; mt++)
#pragma unroll
                for (int nt = 0; nt < 8; nt++)
                    mma16816(acc[mt][nt], a[mt], b[nt]);
        }
        if (++stage == NSTAGE) stage = 0;
    }

    __syncthreads();   // pipeline smem free for epilogue reuse
#pragma unroll
    for (int mt = 0; mt < 2; mt++) {
        int r0 = wm + mt * 16 + (lane >> 2);
#pragma unroll
        for (int nt = 0; nt < 8; nt++)
            fe(r0, wn + nt * 8 + ((lane & 3) << 1), acc[mt][nt]);
    }
}

// ---------------- merged prep: input transpose + weight cvt + rowsum zero ----------------
// grid (64, 16, 17): z<16 -> transpose slice (b = z>>1, which = z&1); z==16 -> weights+rowsum
__global__ __launch_bounds__(256)
void prep_kernel(const float* __restrict__ x, const float* __restrict__ query,
                 const float* __restrict__ kw, const float* __restrict__ qw,
                 const float* __restrict__ vw, const float* __restrict__ uw) {
    int z = blockIdx.z;
    if (z == 16) {
        int idx = (blockIdx.y * 64 + blockIdx.x) * 256 + threadIdx.x;  // [0, 262144)
#pragma unroll
        for (int h = 0; h < 2; h++) {
            int i = idx + h * 262144;
            int seg = i >> 17, off = i & 131071;
            const float* src = seg == 0 ? kw : seg == 1 ? qw : seg == 2 ? vw : uw;
            unsigned short* dst = seg == 0 ? g_Wk : seg == 1 ? g_Wq : seg == 2 ? g_Wv : g_Wu;
            dst[off] = f2bf(src[off]);
        }
        if (idx < Bsz * NN) g_rowsum[idx] = 0.f;
        return;
    }
    int b = z >> 1, which = z & 1;
    const float* src = (which ? query : x) + (size_t)b * CI * NN;
    unsigned short* dst = (which ? g_Qx : g_Xt) + (size_t)b * NN * CI;
    __shared__ unsigned short t[32][33];
    int n0 = blockIdx.x * 32, c0 = blockIdx.y * 32;
    int tx = threadIdx.x & 31, ty = threadIdx.x >> 5;
#pragma unroll
    for (int j = 0; j < 4; j++) {
        int ci = c0 + ty + j * 8;
        t[ty + j * 8][tx] = f2bf(src[(size_t)ci * NN + n0 + tx]);
    }
    __syncthreads();
#pragma unroll
    for (int j = 0; j < 4; j++)
        dst[(size_t)(n0 + ty + j * 8) * CI + c0 + tx] = t[tx][ty + j * 8];
}

// ---------------- Stage 1: ALL projections in one launch ----------------
// z = b*3 + which; which: 0=K -> [n][co]*1/16, 1=Q -> [n][co], 2=V -> [co][n]
__global__ __launch_bounds__(256, 2)
void proj_kernel(const float* __restrict__ kb, const float* __restrict__ qb,
                 const float* __restrict__ vb) {
    int z = blockIdx.z, b = z / 3, which = z - b * 3;
    int co0 = blockIdx.x * 128, n0 = blockIdx.y * 128;

    if (which == 2) {
        const unsigned short* X = g_Xt + (size_t)b * NN * CI;
        unsigned short* out = g_V + (size_t)b * CO * NN;
        gemm_body(CI / BK, g_Wv + (size_t)co0 * CI, CI, X + (size_t)n0 * CI, CI,
            [&](int row, int col, const float* v) {
                float bv0 = vb[co0 + row], bv1 = vb[co0 + row + 8];
                st_bf16x2(out + (size_t)(co0 + row) * NN + n0 + col, v[0] + bv0, v[1] + bv0);
                st_bf16x2(out + (size_t)(co0 + row + 8) * NN + n0 + col, v[2] + bv1, v[3] + bv1);
            });
    } else {
        const unsigned short* X = (which ? g_Qx : g_Xt) + (size_t)b * NN * CI;
        const unsigned short* W = which ? g_Wq : g_Wk;
        const float* bias = which ? qb : kb;
        unsigned short* out = (which ? g_Qt : g_Kt) + (size_t)b * NN * CO;
        float scale = which ? 1.0f : 0.0625f;
        gemm_body(CI / BK, X + (size_t)n0 * CI, CI, W + (size_t)co0 * CI, CI,
            [&](int row, int col, const float* v) {
                float b0 = bias[co0 + col], b1 = bias[co0 + col + 1];
                st_bf16x2(out + (size_t)(n0 + row) * CO + co0 + col,
                          (v[0] + b0) * scale, (v[1] + b1) * scale);
                st_bf16x2(out + (size_t)(n0 + row + 8) * CO + co0 + col,
                          (v[2] + b0) * scale, (v[3] + b1) * scale);
            });
    }
}

// ---------------- Stage 2: S = exp(K.Q/16), rowsum via atomics ----------------
__global__ __launch_bounds__(256, 2)
void qk_kernel() {
    int b = blockIdx.z;
    const unsigned short* Kt = g_Kt + (size_t)b * NN * CO;
    const unsigned short* Qt = g_Qt + (size_t)b * NN * CO;
    unsigned short* S = g_S + (size_t)b * NN * NN;
    int m0 = blockIdx.x * 128, n0 = blockIdx.y * 128;

    float rs[4] = {0.f, 0.f, 0.f, 0.f};
    gemm_body(CO / BK, Kt + (size_t)n0 * CO, CO, Qt + (size_t)m0 * CO, CO,
        [&](int row, int col, const float* v) {
            float e0 = __expf(v[0]), e1 = __expf(v[1]);
            float e2 = __expf(v[2]), e3 = __expf(v[3]);
            st_bf16x2(S + (size_t)(n0 + row) * NN + m0 + col, e0, e1);
            st_bf16x2(S + (size_t)(n0 + row + 8) * NN + m0 + col, e2, e3);
            rs[(row >> 3) & 3] += e0 + e1;
            rs[((row >> 3) & 3) | 1] += e2 + e3;
        });

    int lane = threadIdx.x & 31, wid = threadIdx.x >> 5;
    int wm = (wid & 3) * 32, q = lane >> 2;
#pragma unroll
    for (int i = 0; i < 4; i++) {
        float s = rs[i];
        s += __shfl_xor_sync(0xffffffffu, s, 1);
        s += __shfl_xor_sync(0xffffffffu, s, 2);
        if ((lane & 3) == 0) {
            int row = wm + (i >> 1) * 16 + (i & 1) * 8 + q;
            atomicAdd(&g_rowsum[(size_t)b * NN + n0 + row], s);
        }
    }
}

// ---------------- Stage 3: O/rowsum written DIRECTLY transposed into Ot ----------------
// Tile O[n0+dn][c0+dc] -> Ot[(dn&7)*256 + c0+dc][n0/8 + (dn>>3)].
// Stage in ROW-major smem sT[row][SR]: epilogue writes 4B bf16x2, conflict-free
// (row stride 68 words = 4 mod 32; 8 rows x 4 col-words -> 32 distinct banks).
#define SR 136
__global__ __launch_bounds__(256, 2)
void av_kernel() {
    int b = blockIdx.z;
    const unsigned short* P = g_S + (size_t)b * NN * NN;
    const unsigned short* V = g_V + (size_t)b * CO * NN;
    const float* rsum = g_rowsum + (size_t)b * NN;
    unsigned short* Ot = g_Ot + (size_t)b * NN * CO;
    int c0 = blockIdx.x * 128, n0 = blockIdx.y * 128;
    extern __shared__ __align__(16) unsigned short sm[];
    unsigned short* sT = sm;   // [128 rows][SR halves] = 34816 B, reuses pipeline smem

    gemm_body(NN / BK, P + (size_t)n0 * NN, NN, V + (size_t)c0 * NN, NN,
        [&](int row, int col, const float* v) {
            float i0 = 1.0f / rsum[n0 + row];
            float i1 = 1.0f / rsum[n0 + row + 8];
            st_bf16x2(sT + row * SR + col,       v[0] * i0, v[1] * i0);
            st_bf16x2(sT + (row + 8) * SR + col, v[2] * i1, v[3] * i1);
        });
    __syncthreads();

    int tid = threadIdx.x;
    int co2base = n0 >> 3;
#pragma unroll
    for (int i = 0; i < 4; i++) {
        int seg = tid + i * 256;           // [0,1024): q = dn&7, c = dc
        int q = seg >> 7, c = seg & 127;
        unsigned short vals[16];
#pragma unroll
        for (int s = 0; s < 16; s++)
            vals[s] = sT[(q + 8 * s) * SR + c];   // dn = q + 8s -> co2 = co2base + s
        unsigned short* dst = Ot + (size_t)(q * 256 + c0 + c) * CO + co2base;
        uint4* d4 = reinterpret_cast<uint4*>(dst);
        d4[0] = *reinterpret_cast<uint4*>(vals);
        d4[1] = *reinterpret_cast<uint4*>(vals + 8);
    }
}

// ---------------- Stage 4: up-proj + residual ----------------
__global__ __launch_bounds__(256, 2)
void up_kernel(const float* __restrict__ x, const float* __restrict__ up_b,
               const float* __restrict__ scaling, float* __restrict__ outp) {
    int b = blockIdx.z;
    const unsigned short* Ot = g_Ot + (size_t)b * NN * CO;
    const float* X = x + (size_t)b * CI * NN;
    float* R = outp + (size_t)b * CI * NN;
    int n0 = blockIdx.x * 128, ci0 = blockIdx.y * 128;
    float s = *scaling;

    gemm_body(CO / BK, g_Wu + (size_t)ci0 * CO, CO, Ot + (size_t)n0 * CO, CO,
        [&](int row, int col, const float* v) {
#pragma unroll
            for (int h = 0; h < 2; h++) {
                int ci = ci0 + row + h * 8;
                float bb = up_b[ci];
                const float2 xv = *reinterpret_cast<const float2*>(X + (size_t)ci * NN + n0 + col);
                float2 o;
                o.x = xv.x + s * (v[2 * h] + bb);
                o.y = xv.y + s * (v[2 * h + 1] + bb);
                *reinterpret_cast<float2*>(R + (size_t)ci * NN + n0 + col) = o;
            }
        });
}

// ---------------- launch ----------------
extern "C" void kernel_launch(void* const* d_in, const int* in_sizes, int n_in,
                              void* d_out, int out_size) {
    const float* x       = (const float*)d_in[0];
    const float* query   = (const float*)d_in[1];
    const float* key_w   = (const float*)d_in[2];
    const float* key_b   = (const float*)d_in[3];
    const float* val_w   = (const float*)d_in[4];
    const float* val_b   = (const float*)d_in[5];
    const float* query_w = (const float*)d_in[6];
    const float* query_b = (const float*)d_in[7];
    const float* up_w    = (const float*)d_in[8];
    const float* up_b    = (const float*)d_in[9];
    const float* scaling = (const float*)d_in[10];
    float* out = (float*)d_out;

    cudaFuncSetAttribute(proj_kernel, cudaFuncAttributeMaxDynamicSharedMemorySize, SMEM_BYTES);
    cudaFuncSetAttribute(qk_kernel,   cudaFuncAttributeMaxDynamicSharedMemorySize, SMEM_BYTES);
    cudaFuncSetAttribute(av_kernel,   cudaFuncAttributeMaxDynamicSharedMemorySize, SMEM_BYTES);
    cudaFuncSetAttribute(up_kernel,   cudaFuncAttributeMaxDynamicSharedMemorySize, SMEM_BYTES);

    prep_kernel<<<dim3(NN / 32, CI / 32, Bsz * 2 + 1), 256>>>(x, query, key_w, query_w,
                                                              val_w, up_w);
    proj_kernel<<<dim3(CO / 128, NN / 128, Bsz * 3), 256, SMEM_BYTES>>>(key_b, query_b, val_b);
    qk_kernel<<<dim3(NN / 128, NN / 128, Bsz), 256, SMEM_BYTES>>>();
    av_kernel<<<dim3(CO / 128, NN / 128, Bsz), 256, SMEM_BYTES>>>();
    up_kernel<<<dim3(NN / 128, CI / 128, Bsz), 256, SMEM_BYTES>>>(x, up_b, scaling, out);
}